// round 11
// baseline (speedup 1.0000x reference)
#include <cuda_runtime.h>
#include <cuda_fp16.h>
#include <cstdint>

#define NHID    128
#define TILE_N  32
#define THREADS 256
#define MAXN    100352

// Precomputed per-node hidden contributions:
// per node 512 B = [U: 64 __half2][V: 64 __half2], U = x@W1_top, V = y@W1_bot
__device__ __align__(16) __half2 g_H[(size_t)MAXN * 128];

// ---- kernel1 smem (bytes) ----
#define SM_W     0          // W' fp16: 256 rows x 256 B (init only), reused:
#define SM_T     0          // node tile: 32 x 272
#define SM_STG   8704       // stage: 32 x 528 = 16896 (ends 25600)
#define SM1_TOTAL 65536
#define TRSTR    272
#define SRSTR    528

__device__ __forceinline__ uint32_t smem_u32(const void* p) {
    uint32_t a;
    asm("{ .reg .u64 t; cvta.to.shared.u64 t, %1; cvt.u32.u64 %0, t; }" : "=r"(a) : "l"(p));
    return a;
}
__device__ __forceinline__ void ldsm_x4(uint32_t addr, uint32_t r[4]) {
    asm volatile("ldmatrix.sync.aligned.m8n8.x4.shared.b16 {%0,%1,%2,%3}, [%4];"
                 : "=r"(r[0]), "=r"(r[1]), "=r"(r[2]), "=r"(r[3]) : "r"(addr));
}
__device__ __forceinline__ void mma_fp16(float c[4], const uint32_t a[4], uint32_t b0, uint32_t b1) {
    asm volatile("mma.sync.aligned.m16n8k16.row.col.f32.f16.f16.f32 "
                 "{%0,%1,%2,%3}, {%4,%5,%6,%7}, {%8,%9}, {%0,%1,%2,%3};"
                 : "+f"(c[0]), "+f"(c[1]), "+f"(c[2]), "+f"(c[3])
                 : "r"(a[0]), "r"(a[1]), "r"(a[2]), "r"(a[3]), "r"(b0), "r"(b1));
}
// int32 data -> stride 1; int64 (LE, values < 1e5) -> every odd word 0 -> stride 2
__device__ __forceinline__ int detect_idx_stride(const int* p, int n_words) {
    int stride = 2;
    #pragma unroll 1
    for (int i = 1; i < n_words; i += 2)
        if (p[i] != 0) { stride = 1; break; }
    return stride;
}

// ================= Kernel 1: H[n] = [inputs[n]@W1_top, inputs[n]@W1_bot] (fp16) =================
__global__ void __launch_bounds__(THREADS, 2)
precompute_kernel(const float* __restrict__ inputs,
                  const float* __restrict__ W1,
                  int n_nodes, int n_tiles)
{
    extern __shared__ char smem[];
    const uint32_t sb = smem_u32(smem);
    const int tid = threadIdx.x, lane = tid & 31, wid = tid >> 5;

    // W'[k][j']: j'<128 -> W1[k][j'];  j'>=128 -> W1[128+k][j'-128]
    // stored as W'^T rows j' (256 rows x 128 k fp16 = 256 B/row), XOR-swizzled 16B chunks
    for (int i = tid; i < 256 * 128; i += THREADS) {
        int jp = i >> 7;
        int k  = i & 127;
        float v = (jp < NHID) ? W1[k * NHID + jp] : W1[(NHID + k) * NHID + (jp - NHID)];
        uint32_t off = (uint32_t)jp * 256u + (uint32_t)(((k >> 3) ^ (jp & 7)) << 4)
                     + (uint32_t)(k & 7) * 2u;
        *(__half*)(smem + SM_W + off) = __float2half_rn(v);
    }
    __syncthreads();

    // per-warp A frags: 32 j'-cols (2 m-tiles), all K=128 (8 kc)
    uint32_t aF[8][2][4];
    #pragma unroll
    for (int mt = 0; mt < 2; mt++) {
        uint32_t row = (uint32_t)(wid * 32 + mt * 16 + (lane & 15));
        uint32_t rsw = row & 7;
        #pragma unroll
        for (int kc = 0; kc < 8; kc++) {
            uint32_t chunk = (uint32_t)(2 * kc) + (uint32_t)(lane >> 4);
            ldsm_x4(sb + SM_W + row * 256u + ((chunk ^ rsw) << 4), aF[kc][mt]);
        }
    }
    __syncthreads();   // W' region free -> node tile

    const uint32_t row_l = (uint32_t)((lane & 7) + ((lane >> 4) << 3));
    const uint32_t kb    = (uint32_t)((lane >> 3) & 1);
    const uint32_t eb0   = sb + SM_T + row_l * TRSTR + kb * 16u;
    const uint32_t eb1   = eb0 + 16u * TRSTR;

    const int c4 = tid & 31;   // 16B f32 slot within node row
    const int r0 = tid >> 5;   // 0..7

    for (int tile = blockIdx.x; tile < n_tiles; tile += (int)gridDim.x) {
        const int n0 = tile * TILE_N;
        __syncthreads();   // previous iteration fully done

        // load + convert node tile (32 x 128 f32 -> fp16)
        #pragma unroll
        for (int it = 0; it < 4; it++) {
            int r = r0 + it * 8;
            int node = n0 + r; if (node >= n_nodes) node = n_nodes - 1;
            float4 v = __ldg((const float4*)(inputs + (size_t)node * NHID) + c4);
            __half2 h0 = __float22half2_rn(make_float2(v.x, v.y));
            __half2 h1 = __float22half2_rn(make_float2(v.z, v.w));
            *(uint2*)(smem + SM_T + (uint32_t)r * TRSTR + (uint32_t)c4 * 8u) =
                make_uint2(*(uint32_t*)&h0, *(uint32_t*)&h1);
        }
        __syncthreads();

        float c[2][4][4];
        #pragma unroll
        for (int mt = 0; mt < 2; mt++)
            #pragma unroll
            for (int ng = 0; ng < 4; ng++)
                #pragma unroll
                for (int j = 0; j < 4; j++) c[mt][ng][j] = 0.f;

        #pragma unroll
        for (int kc = 0; kc < 8; kc++) {
            uint32_t f0[4], f1[4];
            ldsm_x4(eb0 + (uint32_t)kc * 32u, f0);
            ldsm_x4(eb1 + (uint32_t)kc * 32u, f1);
            #pragma unroll
            for (int mt = 0; mt < 2; mt++) {
                mma_fp16(c[mt][0], aF[kc][mt], f0[0], f0[1]);
                mma_fp16(c[mt][1], aF[kc][mt], f0[2], f0[3]);
                mma_fp16(c[mt][2], aF[kc][mt], f1[0], f1[1]);
                mma_fp16(c[mt][3], aF[kc][mt], f1[2], f1[3]);
            }
        }

        // stage: c -> fp16 node-major tile [node][j'] (rows 528 B)
        #pragma unroll
        for (int mt = 0; mt < 2; mt++) {
            int j0 = wid * 32 + mt * 16 + (lane >> 2);
            int j1 = j0 + 8;
            #pragma unroll
            for (int ng = 0; ng < 4; ng++) {
                int nA = ng * 8 + 2 * (lane & 3);
                *(__half*)(smem + SM_STG + nA * SRSTR + j0 * 2)       = __float2half_rn(c[mt][ng][0]);
                *(__half*)(smem + SM_STG + (nA + 1) * SRSTR + j0 * 2) = __float2half_rn(c[mt][ng][1]);
                *(__half*)(smem + SM_STG + nA * SRSTR + j1 * 2)       = __float2half_rn(c[mt][ng][2]);
                *(__half*)(smem + SM_STG + (nA + 1) * SRSTR + j1 * 2) = __float2half_rn(c[mt][ng][3]);
            }
        }
        __syncthreads();

        // copy stage -> g_H (coalesced 16B)
        #pragma unroll
        for (int i = 0; i < 4; i++) {
            int s = tid + i * THREADS;
            int n = s >> 5, cc = s & 31;
            int node = n0 + n;
            if (node < n_nodes) {
                uint4 v = *(const uint4*)(smem + SM_STG + (uint32_t)n * SRSTR + (uint32_t)cc * 16u);
                *(uint4*)((char*)g_H + (size_t)node * 512 + (size_t)cc * 16) = v;
            }
        }
    }
}

// ================= Kernel 2: per-edge combine =================
__global__ void __launch_bounds__(256)
edge_kernel(const int* __restrict__ x_idx, const int* __restrict__ y_idx,
            const float* __restrict__ bias1, const float* __restrict__ W2,
            const float* __restrict__ bias2, float* __restrict__ out,
            int n_edges)
{
    const int tid = threadIdx.x;
    const int t   = tid & 7;        // j-chunk: j in [t*16, t*16+16)
    const int es  = tid >> 3;       // edge slot 0..31
    const int e   = blockIdx.x * 32 + es;
    const int ec  = (e < n_edges) ? e : (n_edges - 1);

    const int probe_n = (n_edges >= 64) ? 128 : (2 * n_edges);
    const int istride = detect_idx_stride(x_idx, probe_n);

    float b1r[16], w2r[16];
    #pragma unroll
    for (int i = 0; i < 16; i++) {
        b1r[i] = __ldg(bias1 + t * 16 + i);
        w2r[i] = __ldg(W2 + t * 16 + i);
    }

    const int x = __ldg(x_idx + (size_t)ec * istride);
    const int y = __ldg(y_idx + (size_t)ec * istride);

    const char* Hb = (const char*)g_H;
    uint4 u4[2], v4[2];
    u4[0] = __ldg((const uint4*)(Hb + (size_t)x * 512 + (size_t)t * 32));
    u4[1] = __ldg((const uint4*)(Hb + (size_t)x * 512 + (size_t)t * 32 + 16));
    v4[0] = __ldg((const uint4*)(Hb + (size_t)y * 512 + 256 + (size_t)t * 32));
    v4[1] = __ldg((const uint4*)(Hb + (size_t)y * 512 + 256 + (size_t)t * 32 + 16));

    float s = 0.f;
    #pragma unroll
    for (int h = 0; h < 2; h++) {
        const uint32_t* up = (const uint32_t*)&u4[h];
        const uint32_t* vp = (const uint32_t*)&v4[h];
        #pragma unroll
        for (int w = 0; w < 4; w++) {
            __half2 uh = *(const __half2*)&up[w];
            __half2 vh = *(const __half2*)&vp[w];
            float2 uf = __half22float2(uh);
            float2 vf = __half22float2(vh);
            int i = h * 8 + w * 2;
            s = fmaf(fmaxf(uf.x + vf.x + b1r[i],     0.f), w2r[i],     s);
            s = fmaf(fmaxf(uf.y + vf.y + b1r[i + 1], 0.f), w2r[i + 1], s);
        }
    }
    // reduce over the 8 j-chunk lanes
    s += __shfl_xor_sync(0xffffffffu, s, 1, 8);
    s += __shfl_xor_sync(0xffffffffu, s, 2, 8);
    s += __shfl_xor_sync(0xffffffffu, s, 4, 8);

    if (t == 0 && e < n_edges) {
        float logit = s + __ldg(bias2);
        out[e] = 1.f / (1.f + __expf(-logit));
    }
}

extern "C" void kernel_launch(void* const* d_in, const int* in_sizes, int n_in,
                              void* d_out, int out_size) {
    const float* inputs = (const float*)d_in[0];
    const int*   xi     = (const int*)d_in[1];
    const int*   yi     = (const int*)d_in[2];
    const float* W1     = (const float*)d_in[3];
    const float* b1     = (const float*)d_in[4];
    const float* W2     = (const float*)d_in[5];
    const float* b2     = (const float*)d_in[6];
    float* out = (float*)d_out;

    const int n_nodes = in_sizes[0] / NHID;
    const int n_edges = in_sizes[1];
    const int n_tiles1 = (n_nodes + TILE_N - 1) / TILE_N;

    cudaFuncSetAttribute(precompute_kernel,
                         cudaFuncAttributeMaxDynamicSharedMemorySize, SM1_TOTAL);

    int dev = 0, nsm = 148;
    cudaGetDevice(&dev);
    cudaDeviceGetAttribute(&nsm, cudaDevAttrMultiProcessorCount, dev);

    int grid1 = 2 * nsm;
    if (grid1 > n_tiles1) grid1 = n_tiles1;
    precompute_kernel<<<grid1, THREADS, SM1_TOTAL>>>(inputs, W1, n_nodes, n_tiles1);

    int grid2 = (n_edges + 31) / 32;
    edge_kernel<<<grid2, 256>>>(xi, yi, b1, W2, b2, out, n_edges);
}

// round 12
// speedup vs baseline: 1.4554x; 1.4554x over previous
#include <cuda_runtime.h>
#include <cuda_fp16.h>
#include <cstdint>

#define NHID    128
#define TILE_N  32
#define THREADS 256
#define MAXN    100352

// Precomputed per-node hidden contributions:
// per node 512 B = [U: 128 half][V: 128 half], U = x@W1_top, V = y@W1_bot
__device__ __align__(16) __half2 g_H[(size_t)MAXN * 128];

// ---- kernel1 smem (bytes) ----
#define SM_W     0          // W' fp16: 256 rows x 256 B (init only), reused:
#define SM_T     0          // node tile: 32 x 272
#define SM_STG   8704       // stage: 32 x 528 = 16896 (ends 25600)
#define SM1_TOTAL 65536
#define TRSTR    272
#define SRSTR    528

__device__ __forceinline__ uint32_t smem_u32(const void* p) {
    uint32_t a;
    asm("{ .reg .u64 t; cvta.to.shared.u64 t, %1; cvt.u32.u64 %0, t; }" : "=r"(a) : "l"(p));
    return a;
}
__device__ __forceinline__ void ldsm_x4(uint32_t addr, uint32_t r[4]) {
    asm volatile("ldmatrix.sync.aligned.m8n8.x4.shared.b16 {%0,%1,%2,%3}, [%4];"
                 : "=r"(r[0]), "=r"(r[1]), "=r"(r[2]), "=r"(r[3]) : "r"(addr));
}
__device__ __forceinline__ void mma_fp16(float c[4], const uint32_t a[4], uint32_t b0, uint32_t b1) {
    asm volatile("mma.sync.aligned.m16n8k16.row.col.f32.f16.f16.f32 "
                 "{%0,%1,%2,%3}, {%4,%5,%6,%7}, {%8,%9}, {%0,%1,%2,%3};"
                 : "+f"(c[0]), "+f"(c[1]), "+f"(c[2]), "+f"(c[3])
                 : "r"(a[0]), "r"(a[1]), "r"(a[2]), "r"(a[3]), "r"(b0), "r"(b1));
}
// int32 data -> stride 1; int64 (LE, values < 1e5) -> every odd word 0 -> stride 2
__device__ __forceinline__ int detect_idx_stride(const int* p, int n_words) {
    int stride = 2;
    #pragma unroll 1
    for (int i = 1; i < n_words; i += 2)
        if (p[i] != 0) { stride = 1; break; }
    return stride;
}

// ================= Kernel 1: H[n] = [inputs[n]@W1_top, inputs[n]@W1_bot] (fp16) =================
__global__ void __launch_bounds__(THREADS, 2)
precompute_kernel(const float* __restrict__ inputs,
                  const float* __restrict__ W1,
                  int n_nodes, int n_tiles)
{
    extern __shared__ char smem[];
    const uint32_t sb = smem_u32(smem);
    const int tid = threadIdx.x, lane = tid & 31, wid = tid >> 5;

    // W'[k][j']: j'<128 -> W1[k][j'];  j'>=128 -> W1[128+k][j'-128]
    // stored as W'^T rows j' (256 rows x 128 k fp16 = 256 B/row), XOR-swizzled 16B chunks
    for (int i = tid; i < 256 * 128; i += THREADS) {
        int jp = i >> 7;
        int k  = i & 127;
        float v = (jp < NHID) ? W1[k * NHID + jp] : W1[(NHID + k) * NHID + (jp - NHID)];
        uint32_t off = (uint32_t)jp * 256u + (uint32_t)(((k >> 3) ^ (jp & 7)) << 4)
                     + (uint32_t)(k & 7) * 2u;
        *(__half*)(smem + SM_W + off) = __float2half_rn(v);
    }
    __syncthreads();

    // per-warp A frags: 32 j'-cols (2 m-tiles), all K=128 (8 kc)
    uint32_t aF[8][2][4];
    #pragma unroll
    for (int mt = 0; mt < 2; mt++) {
        uint32_t row = (uint32_t)(wid * 32 + mt * 16 + (lane & 15));
        uint32_t rsw = row & 7;
        #pragma unroll
        for (int kc = 0; kc < 8; kc++) {
            uint32_t chunk = (uint32_t)(2 * kc) + (uint32_t)(lane >> 4);
            ldsm_x4(sb + SM_W + row * 256u + ((chunk ^ rsw) << 4), aF[kc][mt]);
        }
    }
    __syncthreads();   // W' region free -> node tile

    const uint32_t row_l = (uint32_t)((lane & 7) + ((lane >> 4) << 3));
    const uint32_t kb    = (uint32_t)((lane >> 3) & 1);
    const uint32_t eb0   = sb + SM_T + row_l * TRSTR + kb * 16u;
    const uint32_t eb1   = eb0 + 16u * TRSTR;

    const int c4 = tid & 31;   // 16B f32 slot within node row
    const int r0 = tid >> 5;   // 0..7
    const int stride_t = (int)gridDim.x;

    // prologue: prefetch first tile into regs
    float4 st[4];
    if (blockIdx.x < n_tiles) {
        int n0 = blockIdx.x * TILE_N;
        #pragma unroll
        for (int it = 0; it < 4; it++) {
            int node = n0 + r0 + it * 8; if (node >= n_nodes) node = n_nodes - 1;
            st[it] = __ldg((const float4*)(inputs + (size_t)node * NHID) + c4);
        }
    }

    for (int tile = blockIdx.x; tile < n_tiles; tile += stride_t) {
        const int n0 = tile * TILE_N;

        // convert regs -> node tile fp16
        #pragma unroll
        for (int it = 0; it < 4; it++) {
            float4 v = st[it];
            __half2 h0 = __float22half2_rn(make_float2(v.x, v.y));
            __half2 h1 = __float22half2_rn(make_float2(v.z, v.w));
            *(uint2*)(smem + SM_T + (uint32_t)(r0 + it * 8) * TRSTR + (uint32_t)c4 * 8u) =
                make_uint2(*(uint32_t*)&h0, *(uint32_t*)&h1);
        }
        __syncthreads();   // T ready; prev copyout done

        // prefetch next tile (latency hides under MMA/stage/copyout)
        {
            int ntile = tile + stride_t;
            if (ntile < n_tiles) {
                int nn0 = ntile * TILE_N;
                #pragma unroll
                for (int it = 0; it < 4; it++) {
                    int node = nn0 + r0 + it * 8; if (node >= n_nodes) node = n_nodes - 1;
                    st[it] = __ldg((const float4*)(inputs + (size_t)node * NHID) + c4);
                }
            }
        }

        float c[2][4][4];
        #pragma unroll
        for (int mt = 0; mt < 2; mt++)
            #pragma unroll
            for (int ng = 0; ng < 4; ng++)
                #pragma unroll
                for (int j = 0; j < 4; j++) c[mt][ng][j] = 0.f;

        #pragma unroll
        for (int kc = 0; kc < 8; kc++) {
            uint32_t f0[4], f1[4];
            ldsm_x4(eb0 + (uint32_t)kc * 32u, f0);
            ldsm_x4(eb1 + (uint32_t)kc * 32u, f1);
            #pragma unroll
            for (int mt = 0; mt < 2; mt++) {
                mma_fp16(c[mt][0], aF[kc][mt], f0[0], f0[1]);
                mma_fp16(c[mt][1], aF[kc][mt], f0[2], f0[3]);
                mma_fp16(c[mt][2], aF[kc][mt], f1[0], f1[1]);
                mma_fp16(c[mt][3], aF[kc][mt], f1[2], f1[3]);
            }
        }

        // stage: c -> fp16 node-major tile [node][j']
        #pragma unroll
        for (int mt = 0; mt < 2; mt++) {
            int j0 = wid * 32 + mt * 16 + (lane >> 2);
            int j1 = j0 + 8;
            #pragma unroll
            for (int ng = 0; ng < 4; ng++) {
                int nA = ng * 8 + 2 * (lane & 3);
                *(__half*)(smem + SM_STG + nA * SRSTR + j0 * 2)       = __float2half_rn(c[mt][ng][0]);
                *(__half*)(smem + SM_STG + (nA + 1) * SRSTR + j0 * 2) = __float2half_rn(c[mt][ng][1]);
                *(__half*)(smem + SM_STG + nA * SRSTR + j1 * 2)       = __float2half_rn(c[mt][ng][2]);
                *(__half*)(smem + SM_STG + (nA + 1) * SRSTR + j1 * 2) = __float2half_rn(c[mt][ng][3]);
            }
        }
        __syncthreads();   // STG ready

        // copy stage -> g_H (coalesced 16B)
        #pragma unroll
        for (int i = 0; i < 4; i++) {
            int s = tid + i * THREADS;
            int n = s >> 5, cc = s & 31;
            int node = n0 + n;
            if (node < n_nodes) {
                uint4 v = *(const uint4*)(smem + SM_STG + (uint32_t)n * SRSTR + (uint32_t)cc * 16u);
                *(uint4*)((char*)g_H + (size_t)node * 512 + (size_t)cc * 16) = v;
            }
        }
    }
}

// ================= Kernel 2: per-edge combine (grid-stride, consts amortized) =================
__global__ void __launch_bounds__(256)
edge_kernel(const int* __restrict__ x_idx, const int* __restrict__ y_idx,
            const float* __restrict__ bias1, const float* __restrict__ W2,
            const float* __restrict__ bias2, float* __restrict__ out,
            int n_edges)
{
    const int tid = threadIdx.x;
    const int t   = tid & 7;        // j-chunk: j in [t*16, t*16+16)

    const int probe_n = (n_edges >= 64) ? 128 : (2 * n_edges);
    const int istride = detect_idx_stride(x_idx, probe_n);

    float b1r[16], w2r[16];
    #pragma unroll
    for (int i = 0; i < 16; i++) {
        b1r[i] = __ldg(bias1 + t * 16 + i);
        w2r[i] = __ldg(W2 + t * 16 + i);
    }
    const float b2v = __ldg(bias2);
    const char* Hb = (const char*)g_H;

    const int gstart  = (int)((blockIdx.x * 256u + tid) >> 3);
    const int gstride = (int)((gridDim.x * 256u) >> 3);

    for (int e = gstart; e < n_edges; e += gstride) {
        const int x = __ldg(x_idx + (size_t)e * istride);
        const int y = __ldg(y_idx + (size_t)e * istride);

        uint4 u4[2], v4[2];
        u4[0] = __ldg((const uint4*)(Hb + (size_t)x * 512 + (size_t)t * 32));
        u4[1] = __ldg((const uint4*)(Hb + (size_t)x * 512 + (size_t)t * 32 + 16));
        v4[0] = __ldg((const uint4*)(Hb + (size_t)y * 512 + 256 + (size_t)t * 32));
        v4[1] = __ldg((const uint4*)(Hb + (size_t)y * 512 + 256 + (size_t)t * 32 + 16));

        float s = 0.f;
        #pragma unroll
        for (int h = 0; h < 2; h++) {
            const uint32_t* up = (const uint32_t*)&u4[h];
            const uint32_t* vp = (const uint32_t*)&v4[h];
            #pragma unroll
            for (int w = 0; w < 4; w++) {
                float2 uf = __half22float2(*(const __half2*)&up[w]);
                float2 vf = __half22float2(*(const __half2*)&vp[w]);
                int i = h * 8 + w * 2;
                s = fmaf(fmaxf(uf.x + vf.x + b1r[i],     0.f), w2r[i],     s);
                s = fmaf(fmaxf(uf.y + vf.y + b1r[i + 1], 0.f), w2r[i + 1], s);
            }
        }
        s += __shfl_xor_sync(0xffffffffu, s, 1, 8);
        s += __shfl_xor_sync(0xffffffffu, s, 2, 8);
        s += __shfl_xor_sync(0xffffffffu, s, 4, 8);

        if (t == 0)
            out[e] = 1.f / (1.f + __expf(-(s + b2v)));
    }
}

extern "C" void kernel_launch(void* const* d_in, const int* in_sizes, int n_in,
                              void* d_out, int out_size) {
    const float* inputs = (const float*)d_in[0];
    const int*   xi     = (const int*)d_in[1];
    const int*   yi     = (const int*)d_in[2];
    const float* W1     = (const float*)d_in[3];
    const float* b1     = (const float*)d_in[4];
    const float* W2     = (const float*)d_in[5];
    const float* b2     = (const float*)d_in[6];
    float* out = (float*)d_out;

    const int n_nodes = in_sizes[0] / NHID;
    const int n_edges = in_sizes[1];
    const int n_tiles1 = (n_nodes + TILE_N - 1) / TILE_N;

    cudaFuncSetAttribute(precompute_kernel,
                         cudaFuncAttributeMaxDynamicSharedMemorySize, SM1_TOTAL);

    int dev = 0, nsm = 148;
    cudaGetDevice(&dev);
    cudaDeviceGetAttribute(&nsm, cudaDevAttrMultiProcessorCount, dev);

    int grid1 = 2 * nsm;
    if (grid1 > n_tiles1) grid1 = n_tiles1;
    precompute_kernel<<<grid1, THREADS, SM1_TOTAL>>>(inputs, W1, n_nodes, n_tiles1);

    // 8 thread-slots per edge; grid-stride loop (~14 edges per thread at 12 blocks/SM)
    int grid2 = 12 * nsm;
    int max_groups = (n_edges + 31) / 32;
    if (grid2 > max_groups) grid2 = max_groups;
    edge_kernel<<<grid2, 256>>>(xi, yi, b1, W2, b2, out, n_edges);
}

// round 13
// speedup vs baseline: 1.8644x; 1.2811x over previous
#include <cuda_runtime.h>
#include <cuda_fp16.h>
#include <cstdint>

#define NHID    128
#define TILE_N  32
#define THREADS 256
#define MAXN    100352

// Precomputed per-node hidden contributions, 512 B per node:
// [U-block 256 B][V-block 256 B]; within each block, position = g16*16 + q*2 + h
// where the hidden index j = g16*16 + h*8 + q  (g16 in [0,8) for U, [8,16) for V)
__device__ __align__(16) __half2 g_H[(size_t)MAXN * 128];

// ---- kernel1 smem (bytes) ----
#define SM_W     0          // W' fp16: 256 rows x 256 B (init only), reused:
#define SM_T     0          // node tile: 32 x 272
#define SM_STG   8704       // stage: 32 x 528 = 16896 (ends 25600)
#define SM1_TOTAL 65536
#define TRSTR    272
#define SRSTR    528

__device__ __forceinline__ uint32_t smem_u32(const void* p) {
    uint32_t a;
    asm("{ .reg .u64 t; cvta.to.shared.u64 t, %1; cvt.u32.u64 %0, t; }" : "=r"(a) : "l"(p));
    return a;
}
__device__ __forceinline__ void ldsm_x4(uint32_t addr, uint32_t r[4]) {
    asm volatile("ldmatrix.sync.aligned.m8n8.x4.shared.b16 {%0,%1,%2,%3}, [%4];"
                 : "=r"(r[0]), "=r"(r[1]), "=r"(r[2]), "=r"(r[3]) : "r"(addr));
}
__device__ __forceinline__ void mma_fp16(float c[4], const uint32_t a[4], uint32_t b0, uint32_t b1) {
    asm volatile("mma.sync.aligned.m16n8k16.row.col.f32.f16.f16.f32 "
                 "{%0,%1,%2,%3}, {%4,%5,%6,%7}, {%8,%9}, {%0,%1,%2,%3};"
                 : "+f"(c[0]), "+f"(c[1]), "+f"(c[2]), "+f"(c[3])
                 : "r"(a[0]), "r"(a[1]), "r"(a[2]), "r"(a[3]), "r"(b0), "r"(b1));
}
// int32 data -> stride 1; int64 (LE, values < 1e5) -> every odd word 0 -> stride 2
__device__ __forceinline__ int detect_idx_stride(const int* p, int n_words) {
    int stride = 2;
    #pragma unroll 1
    for (int i = 1; i < n_words; i += 2)
        if (p[i] != 0) { stride = 1; break; }
    return stride;
}

// ================= Kernel 1: H[n] = [inputs[n]@W1_top, inputs[n]@W1_bot] (fp16) =================
__global__ void __launch_bounds__(THREADS, 2)
precompute_kernel(const float* __restrict__ inputs,
                  const float* __restrict__ W1,
                  int n_nodes, int n_tiles)
{
    extern __shared__ char smem[];
    const uint32_t sb = smem_u32(smem);
    const int tid = threadIdx.x, lane = tid & 31, wid = tid >> 5;

    // W'[k][j']: j'<128 -> W1[k][j'];  j'>=128 -> W1[128+k][j'-128]
    // stored as W'^T rows j' (256 rows x 128 k fp16 = 256 B/row), XOR-swizzled 16B chunks.
    // COALESCED: consecutive threads read consecutive j' within a W1 row.
    for (int i = tid; i < 128 * 256; i += THREADS) {
        int k  = i >> 8;        // 0..127
        int jp = i & 255;       // 0..255  (fast-varying -> coalesced LDG)
        float v = (jp < NHID) ? W1[k * NHID + jp] : W1[(NHID + k) * NHID + (jp - NHID)];
        uint32_t off = (uint32_t)jp * 256u + (uint32_t)(((k >> 3) ^ (jp & 7)) << 4)
                     + (uint32_t)(k & 7) * 2u;
        *(__half*)(smem + SM_W + off) = __float2half_rn(v);
    }
    __syncthreads();

    // per-warp A frags: 32 j'-cols (2 m-tiles), all K=128 (8 kc)
    uint32_t aF[8][2][4];
    #pragma unroll
    for (int mt = 0; mt < 2; mt++) {
        uint32_t row = (uint32_t)(wid * 32 + mt * 16 + (lane & 15));
        uint32_t rsw = row & 7;
        #pragma unroll
        for (int kc = 0; kc < 8; kc++) {
            uint32_t chunk = (uint32_t)(2 * kc) + (uint32_t)(lane >> 4);
            ldsm_x4(sb + SM_W + row * 256u + ((chunk ^ rsw) << 4), aF[kc][mt]);
        }
    }
    __syncthreads();   // W' region free -> node tile

    const uint32_t row_l = (uint32_t)((lane & 7) + ((lane >> 4) << 3));
    const uint32_t kb    = (uint32_t)((lane >> 3) & 1);
    const uint32_t eb0   = sb + SM_T + row_l * TRSTR + kb * 16u;
    const uint32_t eb1   = eb0 + 16u * TRSTR;

    const int c4 = tid & 31;   // 16B f32 slot within node row
    const int r0 = tid >> 5;   // 0..7
    const int stride_t = (int)gridDim.x;

    // prologue: prefetch first tile into regs
    float4 st[4];
    if (blockIdx.x < n_tiles) {
        int n0 = blockIdx.x * TILE_N;
        #pragma unroll
        for (int it = 0; it < 4; it++) {
            int node = n0 + r0 + it * 8; if (node >= n_nodes) node = n_nodes - 1;
            st[it] = __ldg((const float4*)(inputs + (size_t)node * NHID) + c4);
        }
    }

    for (int tile = blockIdx.x; tile < n_tiles; tile += stride_t) {
        const int n0 = tile * TILE_N;

        // convert regs -> node tile fp16
        #pragma unroll
        for (int it = 0; it < 4; it++) {
            float4 v = st[it];
            __half2 h0 = __float22half2_rn(make_float2(v.x, v.y));
            __half2 h1 = __float22half2_rn(make_float2(v.z, v.w));
            *(uint2*)(smem + SM_T + (uint32_t)(r0 + it * 8) * TRSTR + (uint32_t)c4 * 8u) =
                make_uint2(*(uint32_t*)&h0, *(uint32_t*)&h1);
        }
        __syncthreads();   // T ready; prev copyout done

        // prefetch next tile (latency hides under MMA/stage/copyout)
        {
            int ntile = tile + stride_t;
            if (ntile < n_tiles) {
                int nn0 = ntile * TILE_N;
                #pragma unroll
                for (int it = 0; it < 4; it++) {
                    int node = nn0 + r0 + it * 8; if (node >= n_nodes) node = n_nodes - 1;
                    st[it] = __ldg((const float4*)(inputs + (size_t)node * NHID) + c4);
                }
            }
        }

        float c[2][4][4];
        #pragma unroll
        for (int mt = 0; mt < 2; mt++)
            #pragma unroll
            for (int ng = 0; ng < 4; ng++)
                #pragma unroll
                for (int j = 0; j < 4; j++) c[mt][ng][j] = 0.f;

        #pragma unroll
        for (int kc = 0; kc < 8; kc++) {
            uint32_t f0[4], f1[4];
            ldsm_x4(eb0 + (uint32_t)kc * 32u, f0);
            ldsm_x4(eb1 + (uint32_t)kc * 32u, f1);
            #pragma unroll
            for (int mt = 0; mt < 2; mt++) {
                mma_fp16(c[mt][0], aF[kc][mt], f0[0], f0[1]);
                mma_fp16(c[mt][1], aF[kc][mt], f0[2], f0[3]);
                mma_fp16(c[mt][2], aF[kc][mt], f1[0], f1[1]);
                mma_fp16(c[mt][3], aF[kc][mt], f1[2], f1[3]);
            }
        }

        // stage: packed half2 stores into permuted node layout
        // value (j0, node) pairs: pos = g16*16 + q*2 + h, h=0 -> j0, h=1 -> j1=j0+8
        #pragma unroll
        for (int mt = 0; mt < 2; mt++) {
            int g16 = wid * 2 + mt;
            int q   = lane >> 2;
            uint32_t jb = (uint32_t)(g16 * 32 + q * 4);
            #pragma unroll
            for (int ng = 0; ng < 4; ng++) {
                int nA = ng * 8 + 2 * (lane & 3);
                __half2 pa = __floats2half2_rn(c[mt][ng][0], c[mt][ng][2]);
                __half2 pb = __floats2half2_rn(c[mt][ng][1], c[mt][ng][3]);
                *(__half2*)(smem + SM_STG + (uint32_t)nA * SRSTR + jb)       = pa;
                *(__half2*)(smem + SM_STG + (uint32_t)(nA + 1) * SRSTR + jb) = pb;
            }
        }
        __syncthreads();   // STG ready

        // copy stage -> g_H (coalesced 16B)
        #pragma unroll
        for (int i = 0; i < 4; i++) {
            int s = tid + i * THREADS;
            int n = s >> 5, cc = s & 31;
            int node = n0 + n;
            if (node < n_nodes) {
                uint4 v = *(const uint4*)(smem + SM_STG + (uint32_t)n * SRSTR + (uint32_t)cc * 16u);
                *(uint4*)((char*)g_H + (size_t)node * 512 + (size_t)cc * 16) = v;
            }
        }
    }
}

// ================= Kernel 2: per-edge combine (grid-stride, consts amortized) =================
__global__ void __launch_bounds__(256)
edge_kernel(const int* __restrict__ x_idx, const int* __restrict__ y_idx,
            const float* __restrict__ bias1, const float* __restrict__ W2,
            const float* __restrict__ bias2, float* __restrict__ out,
            int n_edges)
{
    const int tid = threadIdx.x;
    const int t   = tid & 7;        // j-chunk: this thread covers positions [t*16, t*16+16)

    const int probe_n = (n_edges >= 64) ? 128 : (2 * n_edges);
    const int istride = detect_idx_stride(x_idx, probe_n);

    // permuted layout: position-local i -> hidden j = t*16 + (i&1)*8 + (i>>1)
    float b1r[16], w2r[16];
    #pragma unroll
    for (int i = 0; i < 16; i++) {
        int j = t * 16 + (i & 1) * 8 + (i >> 1);
        b1r[i] = __ldg(bias1 + j);
        w2r[i] = __ldg(W2 + j);
    }
    const float b2v = __ldg(bias2);
    const char* Hb = (const char*)g_H;

    const int gstart  = (int)((blockIdx.x * 256u + tid) >> 3);
    const int gstride = (int)((gridDim.x * 256u) >> 3);

    for (int e = gstart; e < n_edges; e += gstride) {
        const int x = __ldg(x_idx + (size_t)e * istride);
        const int y = __ldg(y_idx + (size_t)e * istride);

        uint4 u4[2], v4[2];
        u4[0] = __ldg((const uint4*)(Hb + (size_t)x * 512 + (size_t)t * 32));
        u4[1] = __ldg((const uint4*)(Hb + (size_t)x * 512 + (size_t)t * 32 + 16));
        v4[0] = __ldg((const uint4*)(Hb + (size_t)y * 512 + 256 + (size_t)t * 32));
        v4[1] = __ldg((const uint4*)(Hb + (size_t)y * 512 + 256 + (size_t)t * 32 + 16));

        float s = 0.f;
        #pragma unroll
        for (int h = 0; h < 2; h++) {
            const uint32_t* up = (const uint32_t*)&u4[h];
            const uint32_t* vp = (const uint32_t*)&v4[h];
            #pragma unroll
            for (int w = 0; w < 4; w++) {
                float2 uf = __half22float2(*(const __half2*)&up[w]);
                float2 vf = __half22float2(*(const __half2*)&vp[w]);
                int i = h * 8 + w * 2;
                s = fmaf(fmaxf(uf.x + vf.x + b1r[i],     0.f), w2r[i],     s);
                s = fmaf(fmaxf(uf.y + vf.y + b1r[i + 1], 0.f), w2r[i + 1], s);
            }
        }
        s += __shfl_xor_sync(0xffffffffu, s, 1, 8);
        s += __shfl_xor_sync(0xffffffffu, s, 2, 8);
        s += __shfl_xor_sync(0xffffffffu, s, 4, 8);

        if (t == 0)
            out[e] = 1.f / (1.f + __expf(-(s + b2v)));
    }
}

extern "C" void kernel_launch(void* const* d_in, const int* in_sizes, int n_in,
                              void* d_out, int out_size) {
    const float* inputs = (const float*)d_in[0];
    const int*   xi     = (const int*)d_in[1];
    const int*   yi     = (const int*)d_in[2];
    const float* W1     = (const float*)d_in[3];
    const float* b1     = (const float*)d_in[4];
    const float* W2     = (const float*)d_in[5];
    const float* b2     = (const float*)d_in[6];
    float* out = (float*)d_out;

    const int n_nodes = in_sizes[0] / NHID;
    const int n_edges = in_sizes[1];
    const int n_tiles1 = (n_nodes + TILE_N - 1) / TILE_N;

    cudaFuncSetAttribute(precompute_kernel,
                         cudaFuncAttributeMaxDynamicSharedMemorySize, SM1_TOTAL);

    int dev = 0, nsm = 148;
    cudaGetDevice(&dev);
    cudaDeviceGetAttribute(&nsm, cudaDevAttrMultiProcessorCount, dev);

    int grid1 = 2 * nsm;
    if (grid1 > n_tiles1) grid1 = n_tiles1;
    precompute_kernel<<<grid1, THREADS, SM1_TOTAL>>>(inputs, W1, n_nodes, n_tiles1);

    int grid2 = 12 * nsm;
    int max_groups = (n_edges + 31) / 32;
    if (grid2 > max_groups) grid2 = max_groups;
    edge_kernel<<<grid2, 256>>>(xi, yi, b1, W2, b2, out, n_edges);
}

// round 14
// speedup vs baseline: 2.1525x; 1.1545x over previous
#include <cuda_runtime.h>
#include <cuda_fp16.h>
#include <cstdint>

#define NHID    128
#define TILE_N  32
#define THREADS 256
#define MAXN    100352

// Precomputed per-node hidden contributions, 512 B per node:
// [U-block 256 B][V-block 256 B]; within each block, position = g16*16 + q*2 + h
// hidden index j = (g16 & 7)*16 + h*8 + q;  U-block already includes bias1.
__device__ __align__(16) __half2 g_H[(size_t)MAXN * 128];

// ---- kernel1 smem (bytes) ----
#define SM_W     0          // W' fp16: 256 rows x 256 B (init only), reused:
#define SM_T     0          // node tile: 32 x 272
#define SM_STG   8704       // stage: 32 x 528 = 16896 (ends 25600)
#define SM1_TOTAL 65536
#define TRSTR    272
#define SRSTR    528

__device__ __forceinline__ uint32_t smem_u32(const void* p) {
    uint32_t a;
    asm("{ .reg .u64 t; cvta.to.shared.u64 t, %1; cvt.u32.u64 %0, t; }" : "=r"(a) : "l"(p));
    return a;
}
__device__ __forceinline__ void ldsm_x4(uint32_t addr, uint32_t r[4]) {
    asm volatile("ldmatrix.sync.aligned.m8n8.x4.shared.b16 {%0,%1,%2,%3}, [%4];"
                 : "=r"(r[0]), "=r"(r[1]), "=r"(r[2]), "=r"(r[3]) : "r"(addr));
}
__device__ __forceinline__ void mma_fp16(float c[4], const uint32_t a[4], uint32_t b0, uint32_t b1) {
    asm volatile("mma.sync.aligned.m16n8k16.row.col.f32.f16.f16.f32 "
                 "{%0,%1,%2,%3}, {%4,%5,%6,%7}, {%8,%9}, {%0,%1,%2,%3};"
                 : "+f"(c[0]), "+f"(c[1]), "+f"(c[2]), "+f"(c[3])
                 : "r"(a[0]), "r"(a[1]), "r"(a[2]), "r"(a[3]), "r"(b0), "r"(b1));
}
// int32 data -> stride 1; int64 (LE, values < 1e5) -> every odd word 0 -> stride 2
__device__ __forceinline__ int detect_idx_stride(const int* p, int n_words) {
    int stride = 2;
    #pragma unroll 1
    for (int i = 1; i < n_words; i += 2)
        if (p[i] != 0) { stride = 1; break; }
    return stride;
}

// ================= Kernel 1: H[n] = [inputs[n]@W1_top + b1, inputs[n]@W1_bot] (fp16) =================
__global__ void __launch_bounds__(THREADS, 2)
precompute_kernel(const float* __restrict__ inputs,
                  const float* __restrict__ W1,
                  const float* __restrict__ bias1,
                  int n_nodes, int n_tiles)
{
    extern __shared__ char smem[];
    const uint32_t sb = smem_u32(smem);
    const int tid = threadIdx.x, lane = tid & 31, wid = tid >> 5;

    // W'[k][j']: j'<128 -> W1[k][j'];  j'>=128 -> W1[128+k][j'-128]
    // stored as W'^T rows j' (256 rows x 128 k fp16 = 256 B/row), XOR-swizzled 16B chunks.
    // Coalesced: consecutive threads read consecutive j' within a W1 row.
    for (int i = tid; i < 128 * 256; i += THREADS) {
        int k  = i >> 8;        // 0..127
        int jp = i & 255;       // 0..255 (fast-varying -> coalesced LDG)
        float v = (jp < NHID) ? W1[k * NHID + jp] : W1[(NHID + k) * NHID + (jp - NHID)];
        uint32_t off = (uint32_t)jp * 256u + (uint32_t)(((k >> 3) ^ (jp & 7)) << 4)
                     + (uint32_t)(k & 7) * 2u;
        *(__half*)(smem + SM_W + off) = __float2half_rn(v);
    }
    __syncthreads();

    // per-warp A frags: 32 j'-cols (2 m-tiles), all K=128 (8 kc)
    uint32_t aF[8][2][4];
    #pragma unroll
    for (int mt = 0; mt < 2; mt++) {
        uint32_t row = (uint32_t)(wid * 32 + mt * 16 + (lane & 15));
        uint32_t rsw = row & 7;
        #pragma unroll
        for (int kc = 0; kc < 8; kc++) {
            uint32_t chunk = (uint32_t)(2 * kc) + (uint32_t)(lane >> 4);
            ldsm_x4(sb + SM_W + row * 256u + ((chunk ^ rsw) << 4), aF[kc][mt]);
        }
    }

    // bias fold constants (U block only: g16 = wid*2+mt < 8)
    float bfold[2][2];
    #pragma unroll
    for (int mt = 0; mt < 2; mt++) {
        int g16 = wid * 2 + mt;
        int q   = lane >> 2;
        if (g16 < 8) {
            bfold[mt][0] = __ldg(bias1 + g16 * 16 + q);      // h=0 -> j = g16*16 + q
            bfold[mt][1] = __ldg(bias1 + g16 * 16 + 8 + q);  // h=1 -> j = g16*16 + 8 + q
        } else {
            bfold[mt][0] = 0.f;
            bfold[mt][1] = 0.f;
        }
    }
    __syncthreads();   // W' region free -> node tile

    const uint32_t row_l = (uint32_t)((lane & 7) + ((lane >> 4) << 3));
    const uint32_t kb    = (uint32_t)((lane >> 3) & 1);
    const uint32_t eb0   = sb + SM_T + row_l * TRSTR + kb * 16u;
    const uint32_t eb1   = eb0 + 16u * TRSTR;

    const int c4 = tid & 31;   // 16B f32 slot within node row
    const int r0 = tid >> 5;   // 0..7
    const int stride_t = (int)gridDim.x;

    // prologue: prefetch first tile into regs
    float4 st[4];
    if (blockIdx.x < n_tiles) {
        int n0 = blockIdx.x * TILE_N;
        #pragma unroll
        for (int it = 0; it < 4; it++) {
            int node = n0 + r0 + it * 8; if (node >= n_nodes) node = n_nodes - 1;
            st[it] = __ldg((const float4*)(inputs + (size_t)node * NHID) + c4);
        }
    }

    for (int tile = blockIdx.x; tile < n_tiles; tile += stride_t) {
        const int n0 = tile * TILE_N;

        // convert regs -> node tile fp16
        #pragma unroll
        for (int it = 0; it < 4; it++) {
            float4 v = st[it];
            __half2 h0 = __float22half2_rn(make_float2(v.x, v.y));
            __half2 h1 = __float22half2_rn(make_float2(v.z, v.w));
            *(uint2*)(smem + SM_T + (uint32_t)(r0 + it * 8) * TRSTR + (uint32_t)c4 * 8u) =
                make_uint2(*(uint32_t*)&h0, *(uint32_t*)&h1);
        }
        __syncthreads();   // T ready; prev copyout done

        // prefetch next tile (latency hides under MMA/stage/copyout)
        {
            int ntile = tile + stride_t;
            if (ntile < n_tiles) {
                int nn0 = ntile * TILE_N;
                #pragma unroll
                for (int it = 0; it < 4; it++) {
                    int node = nn0 + r0 + it * 8; if (node >= n_nodes) node = n_nodes - 1;
                    st[it] = __ldg((const float4*)(inputs + (size_t)node * NHID) + c4);
                }
            }
        }

        float c[2][4][4];
        #pragma unroll
        for (int mt = 0; mt < 2; mt++)
            #pragma unroll
            for (int ng = 0; ng < 4; ng++)
                #pragma unroll
                for (int j = 0; j < 4; j++) c[mt][ng][j] = 0.f;

        #pragma unroll
        for (int kc = 0; kc < 8; kc++) {
            uint32_t f0[4], f1[4];
            ldsm_x4(eb0 + (uint32_t)kc * 32u, f0);
            ldsm_x4(eb1 + (uint32_t)kc * 32u, f1);
            #pragma unroll
            for (int mt = 0; mt < 2; mt++) {
                mma_fp16(c[mt][0], aF[kc][mt], f0[0], f0[1]);
                mma_fp16(c[mt][1], aF[kc][mt], f0[2], f0[3]);
                mma_fp16(c[mt][2], aF[kc][mt], f1[0], f1[1]);
                mma_fp16(c[mt][3], aF[kc][mt], f1[2], f1[3]);
            }
        }

        // stage: packed half2 stores into permuted node layout, bias1 folded into U block
        #pragma unroll
        for (int mt = 0; mt < 2; mt++) {
            int g16 = wid * 2 + mt;
            int q   = lane >> 2;
            uint32_t jb = (uint32_t)(g16 * 32 + q * 4);
            float ba = bfold[mt][0], bb = bfold[mt][1];
            #pragma unroll
            for (int ng = 0; ng < 4; ng++) {
                int nA = ng * 8 + 2 * (lane & 3);
                __half2 pa = __floats2half2_rn(c[mt][ng][0] + ba, c[mt][ng][2] + bb);
                __half2 pb = __floats2half2_rn(c[mt][ng][1] + ba, c[mt][ng][3] + bb);
                *(__half2*)(smem + SM_STG + (uint32_t)nA * SRSTR + jb)       = pa;
                *(__half2*)(smem + SM_STG + (uint32_t)(nA + 1) * SRSTR + jb) = pb;
            }
        }
        __syncthreads();   // STG ready

        // copy stage -> g_H (coalesced 16B)
        #pragma unroll
        for (int i = 0; i < 4; i++) {
            int s = tid + i * THREADS;
            int n = s >> 5, cc = s & 31;
            int node = n0 + n;
            if (node < n_nodes) {
                uint4 v = *(const uint4*)(smem + SM_STG + (uint32_t)n * SRSTR + (uint32_t)cc * 16u);
                *(uint4*)((char*)g_H + (size_t)node * 512 + (size_t)cc * 16) = v;
            }
        }
    }
}

// ================= Kernel 2: per-edge combine (half2 add+relu, fp32 dot) =================
__global__ void __launch_bounds__(256)
edge_kernel(const int* __restrict__ x_idx, const int* __restrict__ y_idx,
            const float* __restrict__ W2, const float* __restrict__ bias2,
            float* __restrict__ out, int n_edges)
{
    const int tid = threadIdx.x;
    const int t   = tid & 7;        // covers positions [t*16, t*16+16)

    const int probe_n = (n_edges >= 64) ? 128 : (2 * n_edges);
    const int istride = detect_idx_stride(x_idx, probe_n);

    // permuted layout: position-local i -> hidden j = t*16 + (i&1)*8 + (i>>1)
    float w2r[16];
    #pragma unroll
    for (int i = 0; i < 16; i++) {
        int j = t * 16 + (i & 1) * 8 + (i >> 1);
        w2r[i] = __ldg(W2 + j);
    }
    const float b2v = __ldg(bias2);
    const char* Hb = (const char*)g_H;
    const __half2 z2 = __floats2half2_rn(0.f, 0.f);

    const int gstart  = (int)((blockIdx.x * 256u + tid) >> 3);
    const int gstride = (int)((gridDim.x * 256u) >> 3);

    for (int e = gstart; e < n_edges; e += gstride) {
        const int x = __ldg(x_idx + (size_t)e * istride);
        const int y = __ldg(y_idx + (size_t)e * istride);

        uint4 u4[2], v4[2];
        u4[0] = __ldg((const uint4*)(Hb + (size_t)x * 512 + (size_t)t * 32));
        u4[1] = __ldg((const uint4*)(Hb + (size_t)x * 512 + (size_t)t * 32 + 16));
        v4[0] = __ldg((const uint4*)(Hb + (size_t)y * 512 + 256 + (size_t)t * 32));
        v4[1] = __ldg((const uint4*)(Hb + (size_t)y * 512 + 256 + (size_t)t * 32 + 16));

        float s = 0.f;
        #pragma unroll
        for (int h = 0; h < 2; h++) {
            const uint32_t* up = (const uint32_t*)&u4[h];
            const uint32_t* vp = (const uint32_t*)&v4[h];
            #pragma unroll
            for (int w = 0; w < 4; w++) {
                __half2 r = __hmax2(__hadd2(*(const __half2*)&up[w],
                                            *(const __half2*)&vp[w]), z2);
                float2 rf = __half22float2(r);
                int i = h * 8 + w * 2;
                s = fmaf(rf.x, w2r[i],     s);
                s = fmaf(rf.y, w2r[i + 1], s);
            }
        }
        s += __shfl_xor_sync(0xffffffffu, s, 1, 8);
        s += __shfl_xor_sync(0xffffffffu, s, 2, 8);
        s += __shfl_xor_sync(0xffffffffu, s, 4, 8);

        if (t == 0)
            out[e] = 1.f / (1.f + __expf(-(s + b2v)));
    }
}

extern "C" void kernel_launch(void* const* d_in, const int* in_sizes, int n_in,
                              void* d_out, int out_size) {
    const float* inputs = (const float*)d_in[0];
    const int*   xi     = (const int*)d_in[1];
    const int*   yi     = (const int*)d_in[2];
    const float* W1     = (const float*)d_in[3];
    const float* b1     = (const float*)d_in[4];
    const float* W2     = (const float*)d_in[5];
    const float* b2     = (const float*)d_in[6];
    float* out = (float*)d_out;

    const int n_nodes = in_sizes[0] / NHID;
    const int n_edges = in_sizes[1];
    const int n_tiles1 = (n_nodes + TILE_N - 1) / TILE_N;

    cudaFuncSetAttribute(precompute_kernel,
                         cudaFuncAttributeMaxDynamicSharedMemorySize, SM1_TOTAL);

    int dev = 0, nsm = 148;
    cudaGetDevice(&dev);
    cudaDeviceGetAttribute(&nsm, cudaDevAttrMultiProcessorCount, dev);

    int grid1 = 2 * nsm;
    if (grid1 > n_tiles1) grid1 = n_tiles1;
    precompute_kernel<<<grid1, THREADS, SM1_TOTAL>>>(inputs, W1, b1, n_nodes, n_tiles1);

    int grid2 = 12 * nsm;
    int max_groups = (n_edges + 31) / 32;
    if (grid2 > max_groups) grid2 = max_groups;
    edge_kernel<<<grid2, 256>>>(xi, yi, W2, b2, out, n_edges);
}